// round 14
// baseline (speedup 1.0000x reference)
#include <cuda_runtime.h>
#include <math.h>

#define BATCH 32
#define SEQ   4096
#define NTOK  (BATCH*SEQ)      // 131072
#define AD    64
#define DCODE 256
#define KCODES 512

// ---------------- packed dual-fp32 FMA (bit-identical per-lane IEEE fma) ----
__device__ __forceinline__ void ffma2(float2& acc, float2 a, float2 b)
{
    unsigned long long A = *reinterpret_cast<unsigned long long*>(&a);
    unsigned long long B = *reinterpret_cast<unsigned long long*>(&b);
    unsigned long long C = *reinterpret_cast<unsigned long long*>(&acc);
    asm("fma.rn.f32x2 %0, %1, %2, %0;" : "+l"(C) : "l"(A), "l"(B));
    acc = *reinterpret_cast<float2*>(&C);
}

// ---------------- warp row-reduce for sum(x^2) (BIT-FROZEN since R7) --------
__device__ __forceinline__ float warp_sumsq_256(const float* __restrict__ row, int lane)
{
    float ax = 0.f, ay = 0.f;
#pragma unroll
    for (int i = 0; i < 4; i++) {
        float v0 = row[64*i + 2*lane + 0];
        float v1 = row[64*i + 2*lane + 1];
        ax = __fadd_rn(ax, __fmul_rn(v0, v0));
        ay = __fadd_rn(ay, __fmul_rn(v1, v1));
    }
    float s = __fadd_rn(ax, ay);
#pragma unroll
    for (int off = 16; off > 0; off >>= 1) {
        float o = __shfl_down_sync(0xffffffffu, s, off);
        s = __fadd_rn(s, o);
    }
    return s;   // valid in lane 0
}

// ---------------- scratch (__device__ globals: allocation-free) -------------
__device__ float g_bufA[NTOK*256];   // widest intermediate (z_e)
__device__ float g_bufB[NTOK*128];
__device__ float g_W_e0[BATCH*64*128];
__device__ float g_W_e1[BATCH*128*64];
__device__ float g_W_e2[BATCH*256*128];
__device__ float g_W_d0[BATCH*128*256];
__device__ float g_W_d1[BATCH*64*128];
__device__ float g_W_d2[BATCH*128*64];
__device__ float        g_cnorm[KCODES];
__device__ unsigned int g_hist[KCODES];
__device__ double       g_sumsq;

// ---------------- codebook norms (FROZEN) + stats reset ---------------------
__global__ __launch_bounds__(256) void cnorm_k(const float* __restrict__ CB)
{
    if (blockIdx.x == 0) {
        for (int i = threadIdx.x; i < KCODES; i += 256) g_hist[i] = 0u;
        if (threadIdx.x == 0) g_sumsq = 0.0;
    }
    int warp = (blockIdx.x * blockDim.x + threadIdx.x) >> 5;  // = code index
    int lane = threadIdx.x & 31;
    if (warp < KCODES) {
        float s = warp_sumsq_256(CB + (long)warp * DCODE, lane);
        if (lane == 0) g_cnorm[warp] = s;
    }
}

// ---------------- merged per-batch weight materialization (FROZEN math) -----
struct BWLayer { const float* bw; const float* aw; const float* ab; float* W; int E; };
struct BWAll   { BWLayer L[6]; int off[7]; };

__global__ __launch_bounds__(256) void build_w_all_k(BWAll P, const float* __restrict__ adapt)
{
    __shared__ float ad[BATCH*AD];
    for (int i = threadIdx.x; i < BATCH*AD; i += 256) ad[i] = adapt[i];
    __syncthreads();

    const int bgroup = blockIdx.x & 3;          // 8 batches per group
    const int ebid   = blockIdx.x >> 2;
    const int eg     = ebid * 256 + threadIdx.x;

    int layer = 0;
#pragma unroll
    for (int l = 0; l < 6; l++) if (eg >= P.off[l+1]) layer = l + 1;
    const BWLayer& L = P.L[layer];
    const int e = eg - P.off[layer];

    float awr[AD];
#pragma unroll
    for (int d = 0; d < AD; d += 4) {
        float4 v = *reinterpret_cast<const float4*>(L.aw + (long)e*AD + d);
        awr[d] = v.x; awr[d+1] = v.y; awr[d+2] = v.z; awr[d+3] = v.w;
    }
    const float base = L.bw[e];
    const float abv  = L.ab[e];
    for (int b = bgroup*8; b < bgroup*8 + 8; b++) {
        float acc = 0.f;
#pragma unroll
        for (int d = 0; d < AD; d++) acc = fmaf(ad[b*AD + d], awr[d], acc);
        acc = __fadd_rn(acc, abv);
        L.W[(long)b*L.E + e] = __fadd_rn(base, acc);
    }
}

// ---------------- liquid GEMM 128x64 (FROZEN per-output math) ---------------
template<int IN, int OUT, int ACT>
__global__ __launch_bounds__(256) void liquid_gemm_k(
    const float* __restrict__ X, const float* __restrict__ Wall,
    const float* __restrict__ bb, float* __restrict__ Y)
{
    const int b  = blockIdx.z;
    const int m0 = blockIdx.x * 128;
    const int n0 = blockIdx.y * 64;
    const float* Xb = X    + ((long)b*SEQ + m0) * IN;
    const float* Wb = Wall + (long)b*OUT*IN + (long)n0*IN;
    float*       Yb = Y    + ((long)b*SEQ + m0) * OUT + n0;

    __shared__ float As[2][16][132];
    __shared__ float Bs[2][16][68];

    const int tid  = threadIdx.x;
    const int ar0 = tid >> 1;
    const int aq0 = (tid & 1) * 8;
    const int br  = tid >> 2;
    const int bq  = (tid & 3) * 4;
    const int ty  = tid >> 4;
    const int tx  = tid & 15;

    float2 acc2[8][2];
#pragma unroll
    for (int i = 0; i < 8; i++) { acc2[i][0] = make_float2(0.f,0.f); acc2[i][1] = make_float2(0.f,0.f); }

    float4 av0 = *reinterpret_cast<const float4*>(Xb + (long)ar0*IN + aq0);
    float4 av1 = *reinterpret_cast<const float4*>(Xb + (long)ar0*IN + aq0 + 4);
    float4 bv  = *reinterpret_cast<const float4*>(Wb + (long)br*IN + bq);

    int cur = 0;
    for (int k0 = 0; k0 < IN; k0 += 16) {
        As[cur][aq0+0][ar0] = av0.x; As[cur][aq0+1][ar0] = av0.y;
        As[cur][aq0+2][ar0] = av0.z; As[cur][aq0+3][ar0] = av0.w;
        As[cur][aq0+4][ar0] = av1.x; As[cur][aq0+5][ar0] = av1.y;
        As[cur][aq0+6][ar0] = av1.z; As[cur][aq0+7][ar0] = av1.w;
        Bs[cur][bq+0][br] = bv.x; Bs[cur][bq+1][br] = bv.y;
        Bs[cur][bq+2][br] = bv.z; Bs[cur][bq+3][br] = bv.w;
        __syncthreads();
        if (k0 + 16 < IN) {
            av0 = *reinterpret_cast<const float4*>(Xb + (long)ar0*IN + k0 + 16 + aq0);
            av1 = *reinterpret_cast<const float4*>(Xb + (long)ar0*IN + k0 + 16 + aq0 + 4);
            bv  = *reinterpret_cast<const float4*>(Wb + (long)br*IN + k0 + 16 + bq);
        }
#pragma unroll
        for (int k = 0; k < 16; k++) {
            float4 alo = *reinterpret_cast<const float4*>(&As[cur][k][ty*8]);
            float4 ahi = *reinterpret_cast<const float4*>(&As[cur][k][ty*8+4]);
            float4 q   = *reinterpret_cast<const float4*>(&Bs[cur][k][tx*4]);
            float2 b0 = make_float2(q.x, q.y);
            float2 b1 = make_float2(q.z, q.w);
            float am[8] = {alo.x, alo.y, alo.z, alo.w, ahi.x, ahi.y, ahi.z, ahi.w};
#pragma unroll
            for (int i = 0; i < 8; i++) {
                float2 ai = make_float2(am[i], am[i]);
                ffma2(acc2[i][0], ai, b0);
                ffma2(acc2[i][1], ai, b1);
            }
        }
        cur ^= 1;
    }

    float bias[4];
#pragma unroll
    for (int j = 0; j < 4; j++) bias[j] = bb[n0 + tx*4 + j];

#pragma unroll
    for (int i = 0; i < 8; i++) {
        const int m = ty*8 + i;
        float accv[4] = { acc2[i][0].x, acc2[i][0].y, acc2[i][1].x, acc2[i][1].y };
#pragma unroll
        for (int j = 0; j < 4; j++) {
            float v = __fadd_rn(accv[j], bias[j]);
            if (ACT == 1) v = fmaxf(v, 0.f);
            if (ACT == 2) v = 1.f / (1.f + expf(-v));
            Yb[(long)m*OUT + tx*4 + j] = v;
        }
    }
}

// ---------------- liquid GEMM 128x128, 8x8 microtile (FROZEN per-output) ----
template<int IN, int OUT, int ACT>
__global__ __launch_bounds__(256) void liquid_gemm128_k(
    const float* __restrict__ X, const float* __restrict__ Wall,
    const float* __restrict__ bb, float* __restrict__ Y)
{
    const int b  = blockIdx.z;
    const int m0 = blockIdx.x * 128;
    const int n0 = blockIdx.y * 128;
    const float* Xb = X    + ((long)b*SEQ + m0) * IN;
    const float* Wb = Wall + (long)b*OUT*IN + (long)n0*IN;
    float*       Yb = Y    + ((long)b*SEQ + m0) * OUT + n0;

    __shared__ float As[2][16][132];   // [k][m]
    __shared__ float Bs[2][16][132];   // [k][n]

    const int tid = threadIdx.x;
    const int r0  = tid >> 1;                 // 0..127 (row for both A and B staging)
    const int q0  = (tid & 1) * 8;            // 0 or 8
    const int ty  = tid >> 4;                 // m group of 8
    const int tx  = tid & 15;                 // n group of 8

    float2 acc2[8][4];
#pragma unroll
    for (int i = 0; i < 8; i++)
#pragma unroll
        for (int h = 0; h < 4; h++) acc2[i][h] = make_float2(0.f,0.f);

    float4 av0 = *reinterpret_cast<const float4*>(Xb + (long)r0*IN + q0);
    float4 av1 = *reinterpret_cast<const float4*>(Xb + (long)r0*IN + q0 + 4);
    float4 bv0 = *reinterpret_cast<const float4*>(Wb + (long)r0*IN + q0);
    float4 bv1 = *reinterpret_cast<const float4*>(Wb + (long)r0*IN + q0 + 4);

    int cur = 0;
    for (int k0 = 0; k0 < IN; k0 += 16) {
        As[cur][q0+0][r0] = av0.x; As[cur][q0+1][r0] = av0.y;
        As[cur][q0+2][r0] = av0.z; As[cur][q0+3][r0] = av0.w;
        As[cur][q0+4][r0] = av1.x; As[cur][q0+5][r0] = av1.y;
        As[cur][q0+6][r0] = av1.z; As[cur][q0+7][r0] = av1.w;
        Bs[cur][q0+0][r0] = bv0.x; Bs[cur][q0+1][r0] = bv0.y;
        Bs[cur][q0+2][r0] = bv0.z; Bs[cur][q0+3][r0] = bv0.w;
        Bs[cur][q0+4][r0] = bv1.x; Bs[cur][q0+5][r0] = bv1.y;
        Bs[cur][q0+6][r0] = bv1.z; Bs[cur][q0+7][r0] = bv1.w;
        __syncthreads();
        if (k0 + 16 < IN) {
            av0 = *reinterpret_cast<const float4*>(Xb + (long)r0*IN + k0 + 16 + q0);
            av1 = *reinterpret_cast<const float4*>(Xb + (long)r0*IN + k0 + 16 + q0 + 4);
            bv0 = *reinterpret_cast<const float4*>(Wb + (long)r0*IN + k0 + 16 + q0);
            bv1 = *reinterpret_cast<const float4*>(Wb + (long)r0*IN + k0 + 16 + q0 + 4);
        }
#pragma unroll
        for (int k = 0; k < 16; k++) {
            float4 alo = *reinterpret_cast<const float4*>(&As[cur][k][ty*8]);
            float4 ahi = *reinterpret_cast<const float4*>(&As[cur][k][ty*8+4]);
            float4 qlo = *reinterpret_cast<const float4*>(&Bs[cur][k][tx*8]);
            float4 qhi = *reinterpret_cast<const float4*>(&Bs[cur][k][tx*8+4]);
            float2 B4[4] = { make_float2(qlo.x,qlo.y), make_float2(qlo.z,qlo.w),
                             make_float2(qhi.x,qhi.y), make_float2(qhi.z,qhi.w) };
            float am[8] = {alo.x, alo.y, alo.z, alo.w, ahi.x, ahi.y, ahi.z, ahi.w};
#pragma unroll
            for (int i = 0; i < 8; i++) {
                float2 ai = make_float2(am[i], am[i]);
#pragma unroll
                for (int h = 0; h < 4; h++) ffma2(acc2[i][h], ai, B4[h]);
            }
        }
        cur ^= 1;
    }

    float bias[8];
#pragma unroll
    for (int j = 0; j < 8; j++) bias[j] = bb[n0 + tx*8 + j];

#pragma unroll
    for (int i = 0; i < 8; i++) {
        const int m = ty*8 + i;
        float accv[8] = { acc2[i][0].x, acc2[i][0].y, acc2[i][1].x, acc2[i][1].y,
                          acc2[i][2].x, acc2[i][2].y, acc2[i][3].x, acc2[i][3].y };
#pragma unroll
        for (int j = 0; j < 8; j++) {
            float v = __fadd_rn(accv[j], bias[j]);
            if (ACT == 1) v = fmaxf(v, 0.f);
            if (ACT == 2) v = 1.f / (1.f + expf(-v));
            Yb[(long)m*OUT + tx*8 + j] = v;
        }
    }
}

// ---------------- VQ argmin + fused gather/loss/hist (R12 config, FROZEN) ---
__global__ __launch_bounds__(256) void vq_argmin_k(
    const float* __restrict__ Z, const float* __restrict__ CB,
    float* __restrict__ zq_out)
{
    extern __shared__ float sm[];
    float (*Zt)[68]    = (float (*)[68])    sm;                         // 256 x 68
    float (*Bs)[16][68]= (float (*)[16][68])(sm + 256*68);              // 2 x 16 x 68
    float (*rv)[17]    = (float (*)[17])    (sm + 256*68 + 2*16*68);    // 64 x 17
    int   (*ri)[17]    = (int   (*)[17])    (sm + 256*68 + 2*16*68 + 64*17);
    float *zn_s        = (float*)           (sm + 256*68 + 2*16*68 + 64*17 + 64*17);
    int   *idx_s       = (int*)             (sm + 256*68 + 2*16*68 + 64*17 + 64*17 + 64);
    float *ws          = (float*)           (sm + 256*68 + 2*16*68 + 64*17 + 64*17 + 64 + 64);

    const int m0  = blockIdx.x * 64;
    const int tid = threadIdx.x;

    // Per-token ||z||^2 from GLOBAL memory — FROZEN values & op order.
    {
        const int warp = tid >> 5;
        const int lane = tid & 31;
        for (int j = 0; j < 8; j++) {
            int tok = warp * 8 + j;
            float s = warp_sumsq_256(Z + (long)(m0 + tok)*DCODE, lane);
            if (lane == 0) zn_s[tok] = s;
        }
    }

    // Stage Z transposed: Zt[k][m].
    for (int i = tid; i < 64*64; i += 256) {
        int m = i >> 6;
        int q = (i & 63) * 4;
        float4 v = *reinterpret_cast<const float4*>(Z + (long)(m0 + m)*DCODE + q);
        Zt[q+0][m] = v.x; Zt[q+1][m] = v.y; Zt[q+2][m] = v.z; Zt[q+3][m] = v.w;
    }
    __syncthreads();

    const int lrow = tid >> 2;
    const int lk4  = (tid & 3) * 4;
    const int ty   = tid >> 4;
    const int tx   = tid & 15;

    float zn[4];
#pragma unroll
    for (int i = 0; i < 4; i++) zn[i] = zn_s[ty*4 + i];

    float bestv[4];
    int   besti[4];
#pragma unroll
    for (int i = 0; i < 4; i++) { bestv[i] = 3.4e38f; besti[i] = 0; }

    int cur = 0;
    float4 pb = *reinterpret_cast<const float4*>(CB + (long)lrow*DCODE + lk4);  // n0=0,k0=0

    for (int n0 = 0; n0 < KCODES; n0 += 64) {
        float2 acc[4][4][2];   // [phase][i][h] — 4-phase chains (FROZEN)
#pragma unroll
        for (int p = 0; p < 4; p++)
#pragma unroll
            for (int i = 0; i < 4; i++) {
                acc[p][i][0] = make_float2(0.f,0.f);
                acc[p][i][1] = make_float2(0.f,0.f);
            }

        for (int k0 = 0; k0 < DCODE; k0 += 16) {
            Bs[cur][lk4+0][lrow] = pb.x; Bs[cur][lk4+1][lrow] = pb.y;
            Bs[cur][lk4+2][lrow] = pb.z; Bs[cur][lk4+3][lrow] = pb.w;
            __syncthreads();
            {
                int nk = k0 + 16, nn = n0;
                if (nk == DCODE) { nk = 0; nn = n0 + 64; }
                if (nn < KCODES)
                    pb = *reinterpret_cast<const float4*>(
                        CB + (long)(nn + lrow)*DCODE + nk + lk4);
            }
#pragma unroll
            for (int k = 0; k < 16; k++) {
                const int p = k & 3;
                float4 a = *reinterpret_cast<const float4*>(&Zt[k0+k][ty*4]);
                float4 q = *reinterpret_cast<const float4*>(&Bs[cur][k][tx*4]);
                float2 b0 = make_float2(q.x, q.y);
                float2 b1 = make_float2(q.z, q.w);
                float2 a0 = make_float2(a.x, a.x);
                float2 a1 = make_float2(a.y, a.y);
                float2 a2 = make_float2(a.z, a.z);
                float2 a3 = make_float2(a.w, a.w);
                ffma2(acc[p][0][0], a0, b0); ffma2(acc[p][0][1], a0, b1);
                ffma2(acc[p][1][0], a1, b0); ffma2(acc[p][1][1], a1, b1);
                ffma2(acc[p][2][0], a2, b0); ffma2(acc[p][2][1], a2, b1);
                ffma2(acc[p][3][0], a3, b0); ffma2(acc[p][3][1], a3, b1);
            }
            cur ^= 1;
        }
#pragma unroll
        for (int j = 0; j < 4; j++) {
            const int code = n0 + tx*4 + j;
            const float cn = g_cnorm[code];
#pragma unroll
            for (int i = 0; i < 4; i++) {
                const int h = j >> 1;
                float c0 = (j & 1) ? acc[0][i][h].y : acc[0][i][h].x;
                float c1 = (j & 1) ? acc[1][i][h].y : acc[1][i][h].x;
                float c2 = (j & 1) ? acc[2][i][h].y : acc[2][i][h].x;
                float c3 = (j & 1) ? acc[3][i][h].y : acc[3][i][h].x;
                float dot = __fadd_rn(__fadd_rn(__fadd_rn(c0, c1), c2), c3);
                float t = __fadd_rn(zn[i], cn);                    // fl(zn + cn)
                float s = __fadd_rn(t, -__fmul_rn(2.f, dot));      // fl(t - 2*dot)
                if (s < bestv[i]) { bestv[i] = s; besti[i] = code; }
            }
        }
    }

    __syncthreads();
#pragma unroll
    for (int i = 0; i < 4; i++) {
        rv[ty*4 + i][tx] = bestv[i];
        ri[ty*4 + i][tx] = besti[i];
    }
    __syncthreads();

    if (tid < 64) {
        float bv2 = rv[tid][0]; int bi = ri[tid][0];
#pragma unroll
        for (int x = 1; x < 16; x++) {
            float v = rv[tid][x]; int ii = ri[tid][x];
            if (v < bv2 || (v == bv2 && ii < bi)) { bv2 = v; bi = ii; }
        }
        idx_s[tid] = bi;
    }
    __syncthreads();

    // -------- fused gather: z_q (straight-through), loss, histogram --------
    float lsum = 0.f;
    for (int i = 0; i < 64; i++) {
        int idx  = idx_s[i];
        float q  = CB[(long)idx*DCODE + tid];   // coalesced row
        float z  = Zt[tid][i];
        float diff = __fadd_rn(q, -z);          // fl(q - z)       (FROZEN)
        lsum += diff * diff;
        zq_out[(long)(m0 + i)*DCODE + tid] = __fadd_rn(z, diff);   // (FROZEN)
    }
#pragma unroll
    for (int o = 16; o > 0; o >>= 1) lsum += __shfl_xor_sync(0xffffffffu, lsum, o);
    if ((tid & 31) == 0) ws[tid >> 5] = lsum;
    __syncthreads();
    if (tid == 0) {
        float s = 0.f;
#pragma unroll
        for (int w = 0; w < 8; w++) s += ws[w];
        atomicAdd(&g_sumsq, (double)s);
    }
    if (tid < 64) atomicAdd(&g_hist[idx_s[tid]], 1u);
}

// ---------------- scalars: vq_loss, perplexity ------------------------------
__global__ void finalize_k(float* __restrict__ scalars)
{
    if (threadIdx.x == 0 && blockIdx.x == 0) {
        double mse = g_sumsq / (double)((long)NTOK * DCODE);
        scalars[0] = (float)(mse * 1.25);
        double H = 0.0;
        for (int k = 0; k < KCODES; k++) {
            double p = (double)g_hist[k] / (double)NTOK;
            H -= p * log(p + 1e-10);
        }
        scalars[1] = (float)exp(H);
    }
}

// ---------------- launch --------------------------------------------------
static float* symaddr(const void* sym)
{
    void* p = nullptr;
    cudaGetSymbolAddress(&p, sym);
    return (float*)p;
}

extern "C" void kernel_launch(void* const* d_in, const int* in_sizes, int n_in,
                              void* d_out, int out_size)
{
    (void)in_sizes; (void)n_in; (void)out_size;

    const float* x        = (const float*)d_in[0];
    const float* adapt    = (const float*)d_in[1];
    const float* e0_bw = (const float*)d_in[2],  *e0_bb = (const float*)d_in[3],
               * e0_aw = (const float*)d_in[4],  *e0_ab = (const float*)d_in[5];
    const float* e1_bw = (const float*)d_in[6],  *e1_bb = (const float*)d_in[7],
               * e1_aw = (const float*)d_in[8],  *e1_ab = (const float*)d_in[9];
    const float* e2_bw = (const float*)d_in[10], *e2_bb = (const float*)d_in[11],
               * e2_aw = (const float*)d_in[12], *e2_ab = (const float*)d_in[13];
    const float* d0_bw = (const float*)d_in[14], *d0_bb = (const float*)d_in[15],
               * d0_aw = (const float*)d_in[16], *d0_ab = (const float*)d_in[17];
    const float* d1_bw = (const float*)d_in[18], *d1_bb = (const float*)d_in[19],
               * d1_aw = (const float*)d_in[20], *d1_ab = (const float*)d_in[21];
    const float* d2_bw = (const float*)d_in[22], *d2_bb = (const float*)d_in[23],
               * d2_aw = (const float*)d_in[24], *d2_ab = (const float*)d_in[25];
    const float* codebook = (const float*)d_in[26];

    float* out     = (float*)d_out;
    float* zq      = out;                       // [32,4096,256]
    float* scalars = out + (long)NTOK * DCODE;  // loss, perplexity
    float* recon   = scalars + 2;               // [32,4096,128]

    float* bufA = symaddr(g_bufA);
    float* bufB = symaddr(g_bufB);
    float* W_e0 = symaddr(g_W_e0);
    float* W_e1 = symaddr(g_W_e1);
    float* W_e2 = symaddr(g_W_e2);
    float* W_d0 = symaddr(g_W_d0);
    float* W_d1 = symaddr(g_W_d1);
    float* W_d2 = symaddr(g_W_d2);

    const dim3 blk(256);

    cnorm_k<<<64, blk>>>(codebook);   // + stats reset

    BWAll P;
    P.L[0] = { e0_bw, e0_aw, e0_ab, W_e0, 64*128 };
    P.L[1] = { e1_bw, e1_aw, e1_ab, W_e1, 128*64 };
    P.L[2] = { e2_bw, e2_aw, e2_ab, W_e2, 256*128 };
    P.L[3] = { d0_bw, d0_aw, d0_ab, W_d0, 128*256 };
    P.L[4] = { d1_bw, d1_aw, d1_ab, W_d1, 64*128 };
    P.L[5] = { d2_bw, d2_aw, d2_ab, W_d2, 128*64 };
    P.off[0] = 0;
    for (int l = 0; l < 6; l++) P.off[l+1] = P.off[l] + P.L[l].E;
    build_w_all_k<<<(98304/256)*4, blk>>>(P, adapt);

    // encoder
    liquid_gemm_k   <128,  64, 1><<<dim3(32, 1, BATCH), blk>>>(x,    W_e0, e0_bb, bufA);
    liquid_gemm128_k< 64, 128, 1><<<dim3(32, 1, BATCH), blk>>>(bufA, W_e1, e1_bb, bufB);
    liquid_gemm128_k<128, 256, 0><<<dim3(32, 2, BATCH), blk>>>(bufB, W_e2, e2_bb, bufA);

    // vector quantization (argmin + fused gather/loss/hist)
    const int vq_smem = (256*68 + 2*16*68 + 64*17 + 64*17 + 64 + 64 + 8) * (int)sizeof(float);
    cudaFuncSetAttribute(vq_argmin_k, cudaFuncAttributeMaxDynamicSharedMemorySize, vq_smem);
    vq_argmin_k<<<NTOK/64, blk, vq_smem>>>(bufA, codebook, zq);

    // decoder
    liquid_gemm128_k<256, 128, 1><<<dim3(32, 1, BATCH), blk>>>(zq,   W_d0, d0_bb, bufB);
    liquid_gemm_k   <128,  64, 1><<<dim3(32, 1, BATCH), blk>>>(bufB, W_d1, d1_bb, bufA);
    liquid_gemm128_k< 64, 128, 2><<<dim3(32, 1, BATCH), blk>>>(bufA, W_d2, d2_bb, recon);

    finalize_k<<<1, 32>>>(scalars);
}

// round 15
// speedup vs baseline: 1.0007x; 1.0007x over previous
#include <cuda_runtime.h>
#include <math.h>

#define BATCH 32
#define SEQ   4096
#define NTOK  (BATCH*SEQ)      // 131072
#define AD    64
#define DCODE 256
#define KCODES 512

// ---------------- packed dual-fp32 FMA (bit-identical per-lane IEEE fma) ----
__device__ __forceinline__ void ffma2(float2& acc, float2 a, float2 b)
{
    unsigned long long A = *reinterpret_cast<unsigned long long*>(&a);
    unsigned long long B = *reinterpret_cast<unsigned long long*>(&b);
    unsigned long long C = *reinterpret_cast<unsigned long long*>(&acc);
    asm("fma.rn.f32x2 %0, %1, %2, %0;" : "+l"(C) : "l"(A), "l"(B));
    acc = *reinterpret_cast<float2*>(&C);
}

// ---------------- warp row-reduce for sum(x^2) (BIT-FROZEN since R7) --------
__device__ __forceinline__ float warp_sumsq_256(const float* __restrict__ row, int lane)
{
    float ax = 0.f, ay = 0.f;
#pragma unroll
    for (int i = 0; i < 4; i++) {
        float v0 = row[64*i + 2*lane + 0];
        float v1 = row[64*i + 2*lane + 1];
        ax = __fadd_rn(ax, __fmul_rn(v0, v0));
        ay = __fadd_rn(ay, __fmul_rn(v1, v1));
    }
    float s = __fadd_rn(ax, ay);
#pragma unroll
    for (int off = 16; off > 0; off >>= 1) {
        float o = __shfl_down_sync(0xffffffffu, s, off);
        s = __fadd_rn(s, o);
    }
    return s;   // valid in lane 0
}

// ---------------- scratch (__device__ globals: allocation-free) -------------
__device__ float g_bufA[NTOK*256];   // widest intermediate (z_e)
__device__ float g_bufB[NTOK*128];
__device__ float g_W_e0[BATCH*64*128];
__device__ float g_W_e1[BATCH*128*64];
__device__ float g_W_e2[BATCH*256*128];
__device__ float g_W_d0[BATCH*128*256];
__device__ float g_W_d1[BATCH*64*128];
__device__ float g_W_d2[BATCH*128*64];
__device__ float g_CBt[DCODE*KCODES];   // codebook transposed: [k][code]
__device__ float        g_cnorm[KCODES];
__device__ unsigned int g_hist[KCODES];
__device__ double       g_sumsq;

// ---------------- codebook norms (FROZEN) + stats reset ---------------------
__global__ __launch_bounds__(256) void cnorm_k(const float* __restrict__ CB)
{
    if (blockIdx.x == 0) {
        for (int i = threadIdx.x; i < KCODES; i += 256) g_hist[i] = 0u;
        if (threadIdx.x == 0) g_sumsq = 0.0;
    }
    int warp = (blockIdx.x * blockDim.x + threadIdx.x) >> 5;  // = code index
    int lane = threadIdx.x & 31;
    if (warp < KCODES) {
        float s = warp_sumsq_256(CB + (long)warp * DCODE, lane);
        if (lane == 0) g_cnorm[warp] = s;
    }
}

__global__ __launch_bounds__(256) void transpose_cb_k(const float* __restrict__ CB)
{
    int idx = blockIdx.x * 256 + threadIdx.x;   // 0 .. 131071
    int k = idx >> 9;          // 0..255
    int c = idx & 511;         // coalesced write along code dim
    g_CBt[(long)k*KCODES + c] = CB[(long)c*DCODE + k];
}

// ---------------- merged per-batch weight materialization (FROZEN math) -----
struct BWLayer { const float* bw; const float* aw; const float* ab; float* W; int E; };
struct BWAll   { BWLayer L[6]; int off[7]; };

__global__ __launch_bounds__(256) void build_w_all_k(BWAll P, const float* __restrict__ adapt)
{
    __shared__ float ad[BATCH*AD];
    for (int i = threadIdx.x; i < BATCH*AD; i += 256) ad[i] = adapt[i];
    __syncthreads();

    const int bgroup = blockIdx.x & 3;          // 8 batches per group
    const int ebid   = blockIdx.x >> 2;
    const int eg     = ebid * 256 + threadIdx.x;

    int layer = 0;
#pragma unroll
    for (int l = 0; l < 6; l++) if (eg >= P.off[l+1]) layer = l + 1;
    const BWLayer& L = P.L[layer];
    const int e = eg - P.off[layer];

    float awr[AD];
#pragma unroll
    for (int d = 0; d < AD; d += 4) {
        float4 v = *reinterpret_cast<const float4*>(L.aw + (long)e*AD + d);
        awr[d] = v.x; awr[d+1] = v.y; awr[d+2] = v.z; awr[d+3] = v.w;
    }
    const float base = L.bw[e];
    const float abv  = L.ab[e];
    for (int b = bgroup*8; b < bgroup*8 + 8; b++) {
        float acc = 0.f;
#pragma unroll
        for (int d = 0; d < AD; d++) acc = fmaf(ad[b*AD + d], awr[d], acc);
        acc = __fadd_rn(acc, abv);
        L.W[(long)b*L.E + e] = __fadd_rn(base, acc);
    }
}

// ---------------- liquid GEMM 128x64, double-buffered (R12 config, FROZEN) --
template<int IN, int OUT, int ACT>
__global__ __launch_bounds__(256) void liquid_gemm_k(
    const float* __restrict__ X, const float* __restrict__ Wall,
    const float* __restrict__ bb, float* __restrict__ Y)
{
    const int b  = blockIdx.z;
    const int m0 = blockIdx.x * 128;
    const int n0 = blockIdx.y * 64;
    const float* Xb = X    + ((long)b*SEQ + m0) * IN;
    const float* Wb = Wall + (long)b*OUT*IN + (long)n0*IN;
    float*       Yb = Y    + ((long)b*SEQ + m0) * OUT + n0;

    __shared__ float As[2][16][132];
    __shared__ float Bs[2][16][68];

    const int tid  = threadIdx.x;
    const int ar0 = tid >> 1;
    const int aq0 = (tid & 1) * 8;
    const int br  = tid >> 2;
    const int bq  = (tid & 3) * 4;
    const int ty  = tid >> 4;
    const int tx  = tid & 15;

    float2 acc2[8][2];
#pragma unroll
    for (int i = 0; i < 8; i++) { acc2[i][0] = make_float2(0.f,0.f); acc2[i][1] = make_float2(0.f,0.f); }

    float4 av0 = *reinterpret_cast<const float4*>(Xb + (long)ar0*IN + aq0);
    float4 av1 = *reinterpret_cast<const float4*>(Xb + (long)ar0*IN + aq0 + 4);
    float4 bv  = *reinterpret_cast<const float4*>(Wb + (long)br*IN + bq);

    int cur = 0;
    for (int k0 = 0; k0 < IN; k0 += 16) {
        As[cur][aq0+0][ar0] = av0.x; As[cur][aq0+1][ar0] = av0.y;
        As[cur][aq0+2][ar0] = av0.z; As[cur][aq0+3][ar0] = av0.w;
        As[cur][aq0+4][ar0] = av1.x; As[cur][aq0+5][ar0] = av1.y;
        As[cur][aq0+6][ar0] = av1.z; As[cur][aq0+7][ar0] = av1.w;
        Bs[cur][bq+0][br] = bv.x; Bs[cur][bq+1][br] = bv.y;
        Bs[cur][bq+2][br] = bv.z; Bs[cur][bq+3][br] = bv.w;
        __syncthreads();
        if (k0 + 16 < IN) {
            av0 = *reinterpret_cast<const float4*>(Xb + (long)ar0*IN + k0 + 16 + aq0);
            av1 = *reinterpret_cast<const float4*>(Xb + (long)ar0*IN + k0 + 16 + aq0 + 4);
            bv  = *reinterpret_cast<const float4*>(Wb + (long)br*IN + k0 + 16 + bq);
        }
#pragma unroll
        for (int k = 0; k < 16; k++) {
            float4 alo = *reinterpret_cast<const float4*>(&As[cur][k][ty*8]);
            float4 ahi = *reinterpret_cast<const float4*>(&As[cur][k][ty*8+4]);
            float4 q   = *reinterpret_cast<const float4*>(&Bs[cur][k][tx*4]);
            float2 b0 = make_float2(q.x, q.y);
            float2 b1 = make_float2(q.z, q.w);
            float am[8] = {alo.x, alo.y, alo.z, alo.w, ahi.x, ahi.y, ahi.z, ahi.w};
#pragma unroll
            for (int i = 0; i < 8; i++) {
                float2 ai = make_float2(am[i], am[i]);
                ffma2(acc2[i][0], ai, b0);
                ffma2(acc2[i][1], ai, b1);
            }
        }
        cur ^= 1;
    }

    float bias[4];
#pragma unroll
    for (int j = 0; j < 4; j++) bias[j] = bb[n0 + tx*4 + j];

#pragma unroll
    for (int i = 0; i < 8; i++) {
        const int m = ty*8 + i;
        float accv[4] = { acc2[i][0].x, acc2[i][0].y, acc2[i][1].x, acc2[i][1].y };
#pragma unroll
        for (int j = 0; j < 4; j++) {
            float v = __fadd_rn(accv[j], bias[j]);
            if (ACT == 1) v = fmaxf(v, 0.f);
            if (ACT == 2) v = 1.f / (1.f + expf(-v));
            Yb[(long)m*OUT + tx*4 + j] = v;
        }
    }
}

// ---------------- VQ argmin + fused gather/loss/hist -------------------------
// Arithmetic BIT-FROZEN: dot = 4 phase chains (k mod 4, ascending, ffma2 from
// zero) folded ((c0+c1)+c2)+c3 via __fadd_rn; score fl(fl(zn+cn)-fl(2*dot));
// ascending code scan, first-min ties; zn warp pattern; gather formulas.
// R15 scheduling: 4 tokens x 8 codes microtile; B staged in smem TRANSPOSED
// (Bs[k][c], from g_CBt) so 8 codes = 2 LDS.128; 1 LDS.128 for 4 tokens.
__global__ __launch_bounds__(256, 1) void vq_argmin_k(
    const float* __restrict__ Z, const float* __restrict__ CB,
    float* __restrict__ zq_out)
{
    extern __shared__ float sm[];
    float (*Zt)[68]     = (float (*)[68])     sm;                        // 256 x 68
    float (*Bs)[16][132]= (float (*)[16][132])(sm + 256*68);             // 2 x 16 x 132
    float (*rv)[17]     = (float (*)[17])     (sm + 256*68 + 2*16*132);  // 64 x 17
    int   (*ri)[17]     = (int   (*)[17])     (sm + 256*68 + 2*16*132 + 64*17);
    float *zn_s         = (float*)            (sm + 256*68 + 2*16*132 + 64*17 + 64*17);
    int   *idx_s        = (int*)              (sm + 256*68 + 2*16*132 + 64*17 + 64*17 + 64);
    float *ws           = (float*)            (sm + 256*68 + 2*16*132 + 64*17 + 64*17 + 64 + 64);

    const int m0  = blockIdx.x * 64;
    const int tid = threadIdx.x;

    // Per-token ||z||^2 from GLOBAL memory — FROZEN values & op order.
    {
        const int warp = tid >> 5;
        const int lane = tid & 31;
        for (int j = 0; j < 8; j++) {
            int tok = warp * 8 + j;
            float s = warp_sumsq_256(Z + (long)(m0 + tok)*DCODE, lane);
            if (lane == 0) zn_s[tok] = s;
        }
    }

    // Stage Z transposed: Zt[k][m].
    for (int i = tid; i < 64*64; i += 256) {
        int m = i >> 6;
        int q = (i & 63) * 4;
        float4 v = *reinterpret_cast<const float4*>(Z + (long)(m0 + m)*DCODE + q);
        Zt[q+0][m] = v.x; Zt[q+1][m] = v.y; Zt[q+2][m] = v.z; Zt[q+3][m] = v.w;
    }
    __syncthreads();

    const int ty = tid >> 4;   // token group (4 tokens)
    const int tx = tid & 15;   // code group (8 codes)
    const int skk = tid >> 4;              // staging: k row 0..15
    const int sc8 = (tid & 15) * 8;        // staging: code offset

    float zn[4];
#pragma unroll
    for (int i = 0; i < 4; i++) zn[i] = zn_s[ty*4 + i];

    float bestv[4];
    int   besti[4];
#pragma unroll
    for (int i = 0; i < 4; i++) { bestv[i] = 3.4e38f; besti[i] = 0; }

    int cur = 0;
    float4 pb0 = *reinterpret_cast<const float4*>(g_CBt + (long)skk*KCODES + sc8);
    float4 pb1 = *reinterpret_cast<const float4*>(g_CBt + (long)skk*KCODES + sc8 + 4);

    for (int ct = 0; ct < 4; ct++) {          // code tiles of 128, ascending
        const int c0 = ct*128 + tx*8;

        float2 acc[4][4][4];   // [phase][token][code-pair] — FROZEN 4-phase chains
#pragma unroll
        for (int p = 0; p < 4; p++)
#pragma unroll
            for (int i = 0; i < 4; i++)
#pragma unroll
                for (int h = 0; h < 4; h++) acc[p][i][h] = make_float2(0.f,0.f);

        for (int k0 = 0; k0 < DCODE; k0 += 16) {
            Bs[cur][skk][sc8+0] = pb0.x; Bs[cur][skk][sc8+1] = pb0.y;
            Bs[cur][skk][sc8+2] = pb0.z; Bs[cur][skk][sc8+3] = pb0.w;
            Bs[cur][skk][sc8+4] = pb1.x; Bs[cur][skk][sc8+5] = pb1.y;
            Bs[cur][skk][sc8+6] = pb1.z; Bs[cur][skk][sc8+7] = pb1.w;
            __syncthreads();
            {
                int nk = k0 + 16, nct = ct;
                if (nk == DCODE) { nk = 0; nct = ct + 1; }
                if (nct < 4) {
                    const float* src = g_CBt + (long)(nk + skk)*KCODES + nct*128 + sc8;
                    pb0 = *reinterpret_cast<const float4*>(src);
                    pb1 = *reinterpret_cast<const float4*>(src + 4);
                }
            }
#pragma unroll
            for (int k = 0; k < 16; k++) {
                const int p = k & 3;
                float4 a   = *reinterpret_cast<const float4*>(&Zt[k0+k][ty*4]);
                float4 qlo = *reinterpret_cast<const float4*>(&Bs[cur][k][tx*8]);
                float4 qhi = *reinterpret_cast<const float4*>(&Bs[cur][k][tx*8+4]);
                float2 B4[4] = { make_float2(qlo.x,qlo.y), make_float2(qlo.z,qlo.w),
                                 make_float2(qhi.x,qhi.y), make_float2(qhi.z,qhi.w) };
                float am[4] = { a.x, a.y, a.z, a.w };
#pragma unroll
                for (int i = 0; i < 4; i++) {
                    float2 ai = make_float2(am[i], am[i]);
#pragma unroll
                    for (int h = 0; h < 4; h++) ffma2(acc[p][i][h], ai, B4[h]);
                }
            }
            cur ^= 1;
        }

        // scores: fold FROZEN ((c0+c1)+c2)+c3; codes ascending (first-min)
#pragma unroll
        for (int j = 0; j < 8; j++) {
            const int code = c0 + j;
            const float cn = g_cnorm[code];
            const int h = j >> 1;
#pragma unroll
            for (int i = 0; i < 4; i++) {
                float p0 = (j & 1) ? acc[0][i][h].y : acc[0][i][h].x;
                float p1 = (j & 1) ? acc[1][i][h].y : acc[1][i][h].x;
                float p2 = (j & 1) ? acc[2][i][h].y : acc[2][i][h].x;
                float p3 = (j & 1) ? acc[3][i][h].y : acc[3][i][h].x;
                float dot = __fadd_rn(__fadd_rn(__fadd_rn(p0, p1), p2), p3);
                float t = __fadd_rn(zn[i], cn);                    // fl(zn + cn)
                float s = __fadd_rn(t, -__fmul_rn(2.f, dot));      // fl(t - 2*dot)
                if (s < bestv[i]) { bestv[i] = s; besti[i] = code; }
            }
        }
    }

    __syncthreads();
#pragma unroll
    for (int i = 0; i < 4; i++) {
        rv[ty*4 + i][tx] = bestv[i];
        ri[ty*4 + i][tx] = besti[i];
    }
    __syncthreads();

    if (tid < 64) {
        float bv2 = rv[tid][0]; int bi = ri[tid][0];
#pragma unroll
        for (int x = 1; x < 16; x++) {
            float v = rv[tid][x]; int ii = ri[tid][x];
            if (v < bv2 || (v == bv2 && ii < bi)) { bv2 = v; bi = ii; }
        }
        idx_s[tid] = bi;
    }
    __syncthreads();

    // -------- fused gather: z_q (straight-through), loss, histogram --------
    float lsum = 0.f;
    for (int i = 0; i < 64; i++) {
        int idx  = idx_s[i];
        float q  = CB[(long)idx*DCODE + tid];   // coalesced row
        float z  = Zt[tid][i];
        float diff = __fadd_rn(q, -z);          // fl(q - z)       (FROZEN)
        lsum += diff * diff;
        zq_out[(long)(m0 + i)*DCODE + tid] = __fadd_rn(z, diff);   // (FROZEN)
    }
#pragma unroll
    for (int o = 16; o > 0; o >>= 1) lsum += __shfl_xor_sync(0xffffffffu, lsum, o);
    if ((tid & 31) == 0) ws[tid >> 5] = lsum;
    __syncthreads();
    if (tid == 0) {
        float s = 0.f;
#pragma unroll
        for (int w = 0; w < 8; w++) s += ws[w];
        atomicAdd(&g_sumsq, (double)s);
    }
    if (tid < 64) atomicAdd(&g_hist[idx_s[tid]], 1u);
}

// ---------------- scalars: vq_loss, perplexity ------------------------------
__global__ void finalize_k(float* __restrict__ scalars)
{
    if (threadIdx.x == 0 && blockIdx.x == 0) {
        double mse = g_sumsq / (double)((long)NTOK * DCODE);
        scalars[0] = (float)(mse * 1.25);
        double H = 0.0;
        for (int k = 0; k < KCODES; k++) {
            double p = (double)g_hist[k] / (double)NTOK;
            H -= p * log(p + 1e-10);
        }
        scalars[1] = (float)exp(H);
    }
}

// ---------------- launch --------------------------------------------------
static float* symaddr(const void* sym)
{
    void* p = nullptr;
    cudaGetSymbolAddress(&p, sym);
    return (float*)p;
}

extern "C" void kernel_launch(void* const* d_in, const int* in_sizes, int n_in,
                              void* d_out, int out_size)
{
    (void)in_sizes; (void)n_in; (void)out_size;

    const float* x        = (const float*)d_in[0];
    const float* adapt    = (const float*)d_in[1];
    const float* e0_bw = (const float*)d_in[2],  *e0_bb = (const float*)d_in[3],
               * e0_aw = (const float*)d_in[4],  *e0_ab = (const float*)d_in[5];
    const float* e1_bw = (const float*)d_in[6],  *e1_bb = (const float*)d_in[7],
               * e1_aw = (const float*)d_in[8],  *e1_ab = (const float*)d_in[9];
    const float* e2_bw = (const float*)d_in[10], *e2_bb = (const float*)d_in[11],
               * e2_aw = (const float*)d_in[12], *e2_ab = (const float*)d_in[13];
    const float* d0_bw = (const float*)d_in[14], *d0_bb = (const float*)d_in[15],
               * d0_aw = (const float*)d_in[16], *d0_ab = (const float*)d_in[17];
    const float* d1_bw = (const float*)d_in[18], *d1_bb = (const float*)d_in[19],
               * d1_aw = (const float*)d_in[20], *d1_ab = (const float*)d_in[21];
    const float* d2_bw = (const float*)d_in[22], *d2_bb = (const float*)d_in[23],
               * d2_aw = (const float*)d_in[24], *d2_ab = (const float*)d_in[25];
    const float* codebook = (const float*)d_in[26];

    float* out     = (float*)d_out;
    float* zq      = out;                       // [32,4096,256]
    float* scalars = out + (long)NTOK * DCODE;  // loss, perplexity
    float* recon   = scalars + 2;               // [32,4096,128]

    float* bufA = symaddr(g_bufA);
    float* bufB = symaddr(g_bufB);
    float* W_e0 = symaddr(g_W_e0);
    float* W_e1 = symaddr(g_W_e1);
    float* W_e2 = symaddr(g_W_e2);
    float* W_d0 = symaddr(g_W_d0);
    float* W_d1 = symaddr(g_W_d1);
    float* W_d2 = symaddr(g_W_d2);

    const dim3 blk(256);

    cnorm_k<<<64, blk>>>(codebook);        // + stats reset
    transpose_cb_k<<<512, blk>>>(codebook);

    BWAll P;
    P.L[0] = { e0_bw, e0_aw, e0_ab, W_e0, 64*128 };
    P.L[1] = { e1_bw, e1_aw, e1_ab, W_e1, 128*64 };
    P.L[2] = { e2_bw, e2_aw, e2_ab, W_e2, 256*128 };
    P.L[3] = { d0_bw, d0_aw, d0_ab, W_d0, 128*256 };
    P.L[4] = { d1_bw, d1_aw, d1_ab, W_d1, 64*128 };
    P.L[5] = { d2_bw, d2_aw, d2_ab, W_d2, 128*64 };
    P.off[0] = 0;
    for (int l = 0; l < 6; l++) P.off[l+1] = P.off[l] + P.L[l].E;
    build_w_all_k<<<(98304/256)*4, blk>>>(P, adapt);

    // encoder (R12 config)
    liquid_gemm_k<128,  64, 1><<<dim3(32, 1, BATCH), blk>>>(x,    W_e0, e0_bb, bufA);
    liquid_gemm_k< 64, 128, 1><<<dim3(32, 2, BATCH), blk>>>(bufA, W_e1, e1_bb, bufB);
    liquid_gemm_k<128, 256, 0><<<dim3(32, 4, BATCH), blk>>>(bufB, W_e2, e2_bb, bufA);

    // vector quantization (argmin + fused gather/loss/hist)
    const int vq_smem = (256*68 + 2*16*132 + 64*17 + 64*17 + 64 + 64 + 8) * (int)sizeof(float); // 95776 B
    cudaFuncSetAttribute(vq_argmin_k, cudaFuncAttributeMaxDynamicSharedMemorySize, vq_smem);
    vq_argmin_k<<<NTOK/64, blk, vq_smem>>>(bufA, codebook, zq);

    // decoder (R12 config)
    liquid_gemm_k<256, 128, 1><<<dim3(32, 2, BATCH), blk>>>(zq,   W_d0, d0_bb, bufB);
    liquid_gemm_k<128,  64, 1><<<dim3(32, 1, BATCH), blk>>>(bufB, W_d1, d1_bb, bufA);
    liquid_gemm_k< 64, 128, 2><<<dim3(32, 2, BATCH), blk>>>(bufA, W_d2, d2_bb, recon);

    finalize_k<<<1, 32>>>(scalars);
}

// round 16
// speedup vs baseline: 1.0551x; 1.0543x over previous
#include <cuda_runtime.h>
#include <math.h>

#define BATCH 32
#define SEQ   4096
#define NTOK  (BATCH*SEQ)      // 131072
#define AD    64
#define DCODE 256
#define KCODES 512

// ---------------- packed dual-fp32 FMA (bit-identical per-lane IEEE fma) ----
__device__ __forceinline__ void ffma2(float2& acc, float2 a, float2 b)
{
    unsigned long long A = *reinterpret_cast<unsigned long long*>(&a);
    unsigned long long B = *reinterpret_cast<unsigned long long*>(&b);
    unsigned long long C = *reinterpret_cast<unsigned long long*>(&acc);
    asm("fma.rn.f32x2 %0, %1, %2, %0;" : "+l"(C) : "l"(A), "l"(B));
    acc = *reinterpret_cast<float2*>(&C);
}

// ---------------- warp row-reduce for sum(x^2) (BIT-FROZEN since R7) --------
__device__ __forceinline__ float warp_sumsq_256(const float* __restrict__ row, int lane)
{
    float ax = 0.f, ay = 0.f;
#pragma unroll
    for (int i = 0; i < 4; i++) {
        float v0 = row[64*i + 2*lane + 0];
        float v1 = row[64*i + 2*lane + 1];
        ax = __fadd_rn(ax, __fmul_rn(v0, v0));
        ay = __fadd_rn(ay, __fmul_rn(v1, v1));
    }
    float s = __fadd_rn(ax, ay);
#pragma unroll
    for (int off = 16; off > 0; off >>= 1) {
        float o = __shfl_down_sync(0xffffffffu, s, off);
        s = __fadd_rn(s, o);
    }
    return s;   // valid in lane 0
}

// ---------------- scratch (__device__ globals: allocation-free) -------------
__device__ float g_bufA[NTOK*256];   // widest intermediate (z_e)
__device__ float g_bufB[NTOK*128];
__device__ float g_W_e0[BATCH*64*128];
__device__ float g_W_e1[BATCH*128*64];
__device__ float g_W_e2[BATCH*256*128];
__device__ float g_W_d0[BATCH*128*256];
__device__ float g_W_d1[BATCH*64*128];
__device__ float g_W_d2[BATCH*128*64];
__device__ float        g_cnorm[KCODES];
__device__ unsigned int g_hist[KCODES];
__device__ double       g_sumsq;

// ---------------- codebook norms (FROZEN) + stats reset ---------------------
__global__ __launch_bounds__(256) void cnorm_k(const float* __restrict__ CB)
{
    if (blockIdx.x == 0) {
        for (int i = threadIdx.x; i < KCODES; i += 256) g_hist[i] = 0u;
        if (threadIdx.x == 0) g_sumsq = 0.0;
    }
    int warp = (blockIdx.x * blockDim.x + threadIdx.x) >> 5;  // = code index
    int lane = threadIdx.x & 31;
    if (warp < KCODES) {
        float s = warp_sumsq_256(CB + (long)warp * DCODE, lane);
        if (lane == 0) g_cnorm[warp] = s;
    }
}

// ---------------- merged per-batch weight materialization (FROZEN math) -----
struct BWLayer { const float* bw; const float* aw; const float* ab; float* W; int E; };
struct BWAll   { BWLayer L[6]; int off[7]; };

__global__ __launch_bounds__(256) void build_w_all_k(BWAll P, const float* __restrict__ adapt)
{
    __shared__ float ad[BATCH*AD];
    for (int i = threadIdx.x; i < BATCH*AD; i += 256) ad[i] = adapt[i];
    __syncthreads();

    const int bgroup = blockIdx.x & 3;          // 8 batches per group
    const int ebid   = blockIdx.x >> 2;
    const int eg     = ebid * 256 + threadIdx.x;

    int layer = 0;
#pragma unroll
    for (int l = 0; l < 6; l++) if (eg >= P.off[l+1]) layer = l + 1;
    const BWLayer& L = P.L[layer];
    const int e = eg - P.off[layer];

    float awr[AD];
#pragma unroll
    for (int d = 0; d < AD; d += 4) {
        float4 v = *reinterpret_cast<const float4*>(L.aw + (long)e*AD + d);
        awr[d] = v.x; awr[d+1] = v.y; awr[d+2] = v.z; awr[d+3] = v.w;
    }
    const float base = L.bw[e];
    const float abv  = L.ab[e];
    for (int b = bgroup*8; b < bgroup*8 + 8; b++) {
        float acc = 0.f;
#pragma unroll
        for (int d = 0; d < AD; d++) acc = fmaf(ad[b*AD + d], awr[d], acc);
        acc = __fadd_rn(acc, abv);
        L.W[(long)b*L.E + e] = __fadd_rn(base, acc);
    }
}

// ---------------- liquid GEMM 128x64, double-buffered (R12 config, FROZEN) --
template<int IN, int OUT, int ACT>
__global__ __launch_bounds__(256) void liquid_gemm_k(
    const float* __restrict__ X, const float* __restrict__ Wall,
    const float* __restrict__ bb, float* __restrict__ Y)
{
    const int b  = blockIdx.z;
    const int m0 = blockIdx.x * 128;
    const int n0 = blockIdx.y * 64;
    const float* Xb = X    + ((long)b*SEQ + m0) * IN;
    const float* Wb = Wall + (long)b*OUT*IN + (long)n0*IN;
    float*       Yb = Y    + ((long)b*SEQ + m0) * OUT + n0;

    __shared__ float As[2][16][132];
    __shared__ float Bs[2][16][68];

    const int tid  = threadIdx.x;
    const int ar0 = tid >> 1;
    const int aq0 = (tid & 1) * 8;
    const int br  = tid >> 2;
    const int bq  = (tid & 3) * 4;
    const int ty  = tid >> 4;
    const int tx  = tid & 15;

    float2 acc2[8][2];
#pragma unroll
    for (int i = 0; i < 8; i++) { acc2[i][0] = make_float2(0.f,0.f); acc2[i][1] = make_float2(0.f,0.f); }

    float4 av0 = *reinterpret_cast<const float4*>(Xb + (long)ar0*IN + aq0);
    float4 av1 = *reinterpret_cast<const float4*>(Xb + (long)ar0*IN + aq0 + 4);
    float4 bv  = *reinterpret_cast<const float4*>(Wb + (long)br*IN + bq);

    int cur = 0;
    for (int k0 = 0; k0 < IN; k0 += 16) {
        As[cur][aq0+0][ar0] = av0.x; As[cur][aq0+1][ar0] = av0.y;
        As[cur][aq0+2][ar0] = av0.z; As[cur][aq0+3][ar0] = av0.w;
        As[cur][aq0+4][ar0] = av1.x; As[cur][aq0+5][ar0] = av1.y;
        As[cur][aq0+6][ar0] = av1.z; As[cur][aq0+7][ar0] = av1.w;
        Bs[cur][bq+0][br] = bv.x; Bs[cur][bq+1][br] = bv.y;
        Bs[cur][bq+2][br] = bv.z; Bs[cur][bq+3][br] = bv.w;
        __syncthreads();
        if (k0 + 16 < IN) {
            av0 = *reinterpret_cast<const float4*>(Xb + (long)ar0*IN + k0 + 16 + aq0);
            av1 = *reinterpret_cast<const float4*>(Xb + (long)ar0*IN + k0 + 16 + aq0 + 4);
            bv  = *reinterpret_cast<const float4*>(Wb + (long)br*IN + k0 + 16 + bq);
        }
#pragma unroll
        for (int k = 0; k < 16; k++) {
            float4 alo = *reinterpret_cast<const float4*>(&As[cur][k][ty*8]);
            float4 ahi = *reinterpret_cast<const float4*>(&As[cur][k][ty*8+4]);
            float4 q   = *reinterpret_cast<const float4*>(&Bs[cur][k][tx*4]);
            float2 b0 = make_float2(q.x, q.y);
            float2 b1 = make_float2(q.z, q.w);
            float am[8] = {alo.x, alo.y, alo.z, alo.w, ahi.x, ahi.y, ahi.z, ahi.w};
#pragma unroll
            for (int i = 0; i < 8; i++) {
                float2 ai = make_float2(am[i], am[i]);
                ffma2(acc2[i][0], ai, b0);
                ffma2(acc2[i][1], ai, b1);
            }
        }
        cur ^= 1;
    }

    float bias[4];
#pragma unroll
    for (int j = 0; j < 4; j++) bias[j] = bb[n0 + tx*4 + j];

#pragma unroll
    for (int i = 0; i < 8; i++) {
        const int m = ty*8 + i;
        float accv[4] = { acc2[i][0].x, acc2[i][0].y, acc2[i][1].x, acc2[i][1].y };
#pragma unroll
        for (int j = 0; j < 4; j++) {
            float v = __fadd_rn(accv[j], bias[j]);
            if (ACT == 1) v = fmaxf(v, 0.f);
            if (ACT == 2) v = 1.f / (1.f + expf(-v));
            Yb[(long)m*OUT + tx*4 + j] = v;
        }
    }
}

// ---------------- VQ argmin + fused gather/loss/hist -------------------------
// R12 arithmetic BIT-FROZEN (4-phase interleaved ffma2 chains, fold
// ((c0+c1)+c2)+c3, score fl(fl(zn+cn)-fl(2*dot)), ascending first-min,
// zn warp pattern, gather formulas). R16: 512 threads / 128 tokens per
// block — per-thread work shape & registers IDENTICAL to R12; B staging
// and barriers amortized over 2x tokens; 16 warps for latency hiding.
__global__ __launch_bounds__(512, 1) void vq_argmin_k(
    const float* __restrict__ Z, const float* __restrict__ CB,
    float* __restrict__ zq_out)
{
    extern __shared__ float sm[];
    float (*Zt)[132]   = (float (*)[132])   sm;                          // 256 x 132
    float (*Bs)[16][68]= (float (*)[16][68])(sm + 256*132);              // 2 x 16 x 68
    float (*rv)[17]    = (float (*)[17])    (sm + 256*132 + 2*16*68);    // 128 x 17
    int   (*ri)[17]    = (int   (*)[17])    (sm + 256*132 + 2*16*68 + 128*17);
    float *zn_s        = (float*)           (sm + 256*132 + 2*16*68 + 128*17 + 128*17);
    int   *idx_s       = (int*)             (sm + 256*132 + 2*16*68 + 128*17 + 128*17 + 128);
    float *ws          = (float*)           (sm + 256*132 + 2*16*68 + 128*17 + 128*17 + 128 + 128);

    const int m0  = blockIdx.x * 128;
    const int tid = threadIdx.x;

    // Per-token ||z||^2 — FROZEN values & op order (16 warps x 8 tokens).
    {
        const int warp = tid >> 5;
        const int lane = tid & 31;
        for (int j = 0; j < 8; j++) {
            int tok = warp * 8 + j;
            float s = warp_sumsq_256(Z + (long)(m0 + tok)*DCODE, lane);
            if (lane == 0) zn_s[tok] = s;
        }
    }

    // Stage Z transposed: Zt[k][m], 128 tokens.
    for (int i = tid; i < 128*64; i += 512) {
        int m = i >> 6;
        int q = (i & 63) * 4;
        float4 v = *reinterpret_cast<const float4*>(Z + (long)(m0 + m)*DCODE + q);
        Zt[q+0][m] = v.x; Zt[q+1][m] = v.y; Zt[q+2][m] = v.z; Zt[q+3][m] = v.w;
    }
    __syncthreads();

    const int lrow = tid >> 2;          // staging (tid<256 only): code row 0..63
    const int lk4  = (tid & 3) * 4;
    const int ty   = tid >> 4;          // 0..31 token group
    const int tx   = tid & 15;          // 0..15 code group

    float zn[4];
#pragma unroll
    for (int i = 0; i < 4; i++) zn[i] = zn_s[ty*4 + i];

    float bestv[4];
    int   besti[4];
#pragma unroll
    for (int i = 0; i < 4; i++) { bestv[i] = 3.4e38f; besti[i] = 0; }

    int cur = 0;
    float4 pb;
    if (tid < 256)
        pb = *reinterpret_cast<const float4*>(CB + (long)lrow*DCODE + lk4);  // n0=0,k0=0

    for (int n0 = 0; n0 < KCODES; n0 += 64) {
        float2 acc[4][4][2];   // [phase][token][half] — FROZEN 4-phase chains
#pragma unroll
        for (int p = 0; p < 4; p++)
#pragma unroll
            for (int i = 0; i < 4; i++) {
                acc[p][i][0] = make_float2(0.f,0.f);
                acc[p][i][1] = make_float2(0.f,0.f);
            }

        for (int k0 = 0; k0 < DCODE; k0 += 16) {
            if (tid < 256) {
                Bs[cur][lk4+0][lrow] = pb.x; Bs[cur][lk4+1][lrow] = pb.y;
                Bs[cur][lk4+2][lrow] = pb.z; Bs[cur][lk4+3][lrow] = pb.w;
            }
            __syncthreads();
            if (tid < 256) {
                int nk = k0 + 16, nn = n0;
                if (nk == DCODE) { nk = 0; nn = n0 + 64; }
                if (nn < KCODES)
                    pb = *reinterpret_cast<const float4*>(
                        CB + (long)(nn + lrow)*DCODE + nk + lk4);
            }
#pragma unroll
            for (int k = 0; k < 16; k++) {
                const int p = k & 3;
                float4 a = *reinterpret_cast<const float4*>(&Zt[k0+k][ty*4]);
                float4 q = *reinterpret_cast<const float4*>(&Bs[cur][k][tx*4]);
                float2 b0 = make_float2(q.x, q.y);
                float2 b1 = make_float2(q.z, q.w);
                float2 a0 = make_float2(a.x, a.x);
                float2 a1 = make_float2(a.y, a.y);
                float2 a2 = make_float2(a.z, a.z);
                float2 a3 = make_float2(a.w, a.w);
                ffma2(acc[p][0][0], a0, b0); ffma2(acc[p][0][1], a0, b1);
                ffma2(acc[p][1][0], a1, b0); ffma2(acc[p][1][1], a1, b1);
                ffma2(acc[p][2][0], a2, b0); ffma2(acc[p][2][1], a2, b1);
                ffma2(acc[p][3][0], a3, b0); ffma2(acc[p][3][1], a3, b1);
            }
            cur ^= 1;
        }
#pragma unroll
        for (int j = 0; j < 4; j++) {
            const int code = n0 + tx*4 + j;
            const float cn = g_cnorm[code];
#pragma unroll
            for (int i = 0; i < 4; i++) {
                const int h = j >> 1;
                float c0 = (j & 1) ? acc[0][i][h].y : acc[0][i][h].x;
                float c1 = (j & 1) ? acc[1][i][h].y : acc[1][i][h].x;
                float c2 = (j & 1) ? acc[2][i][h].y : acc[2][i][h].x;
                float c3 = (j & 1) ? acc[3][i][h].y : acc[3][i][h].x;
                float dot = __fadd_rn(__fadd_rn(__fadd_rn(c0, c1), c2), c3);
                float t = __fadd_rn(zn[i], cn);                    // fl(zn + cn)
                float s = __fadd_rn(t, -__fmul_rn(2.f, dot));      // fl(t - 2*dot)
                if (s < bestv[i]) { bestv[i] = s; besti[i] = code; }
            }
        }
    }

    __syncthreads();
#pragma unroll
    for (int i = 0; i < 4; i++) {
        rv[ty*4 + i][tx] = bestv[i];
        ri[ty*4 + i][tx] = besti[i];
    }
    __syncthreads();

    if (tid < 128) {
        float bv2 = rv[tid][0]; int bi = ri[tid][0];
#pragma unroll
        for (int x = 1; x < 16; x++) {
            float v = rv[tid][x]; int ii = ri[tid][x];
            if (v < bv2 || (v == bv2 && ii < bi)) { bv2 = v; bi = ii; }
        }
        idx_s[tid] = bi;
    }
    __syncthreads();

    // -------- fused gather: z_q (straight-through), loss, histogram --------
    // Threads 0..255 handle tokens 0..63 (d = tid); 256..511 tokens 64..127.
    {
        const int d    = tid & 255;
        const int tbase = (tid >> 8) * 64;
        float lsum = 0.f;
        for (int i = 0; i < 64; i++) {
            int token = tbase + i;
            int idx  = idx_s[token];
            float q  = CB[(long)idx*DCODE + d];
            float z  = Zt[d][token];
            float diff = __fadd_rn(q, -z);        // fl(q - z)     (FROZEN)
            lsum += diff * diff;
            zq_out[(long)(m0 + token)*DCODE + d] = __fadd_rn(z, diff);  // (FROZEN)
        }
#pragma unroll
        for (int o = 16; o > 0; o >>= 1) lsum += __shfl_xor_sync(0xffffffffu, lsum, o);
        if ((tid & 31) == 0) ws[tid >> 5] = lsum;
    }
    __syncthreads();
    if (tid == 0) {
        float s = 0.f;
#pragma unroll
        for (int w = 0; w < 16; w++) s += ws[w];
        atomicAdd(&g_sumsq, (double)s);
    }
    if (tid < 128) atomicAdd(&g_hist[idx_s[tid]], 1u);
}

// ---------------- scalars: vq_loss, perplexity ------------------------------
__global__ void finalize_k(float* __restrict__ scalars)
{
    if (threadIdx.x == 0 && blockIdx.x == 0) {
        double mse = g_sumsq / (double)((long)NTOK * DCODE);
        scalars[0] = (float)(mse * 1.25);
        double H = 0.0;
        for (int k = 0; k < KCODES; k++) {
            double p = (double)g_hist[k] / (double)NTOK;
            H -= p * log(p + 1e-10);
        }
        scalars[1] = (float)exp(H);
    }
}

// ---------------- launch --------------------------------------------------
static float* symaddr(const void* sym)
{
    void* p = nullptr;
    cudaGetSymbolAddress(&p, sym);
    return (float*)p;
}

extern "C" void kernel_launch(void* const* d_in, const int* in_sizes, int n_in,
                              void* d_out, int out_size)
{
    (void)in_sizes; (void)n_in; (void)out_size;

    const float* x        = (const float*)d_in[0];
    const float* adapt    = (const float*)d_in[1];
    const float* e0_bw = (const float*)d_in[2],  *e0_bb = (const float*)d_in[3],
               * e0_aw = (const float*)d_in[4],  *e0_ab = (const float*)d_in[5];
    const float* e1_bw = (const float*)d_in[6],  *e1_bb = (const float*)d_in[7],
               * e1_aw = (const float*)d_in[8],  *e1_ab = (const float*)d_in[9];
    const float* e2_bw = (const float*)d_in[10], *e2_bb = (const float*)d_in[11],
               * e2_aw = (const float*)d_in[12], *e2_ab = (const float*)d_in[13];
    const float* d0_bw = (const float*)d_in[14], *d0_bb = (const float*)d_in[15],
               * d0_aw = (const float*)d_in[16], *d0_ab = (const float*)d_in[17];
    const float* d1_bw = (const float*)d_in[18], *d1_bb = (const float*)d_in[19],
               * d1_aw = (const float*)d_in[20], *d1_ab = (const float*)d_in[21];
    const float* d2_bw = (const float*)d_in[22], *d2_bb = (const float*)d_in[23],
               * d2_aw = (const float*)d_in[24], *d2_ab = (const float*)d_in[25];
    const float* codebook = (const float*)d_in[26];

    float* out     = (float*)d_out;
    float* zq      = out;                       // [32,4096,256]
    float* scalars = out + (long)NTOK * DCODE;  // loss, perplexity
    float* recon   = scalars + 2;               // [32,4096,128]

    float* bufA = symaddr(g_bufA);
    float* bufB = symaddr(g_bufB);
    float* W_e0 = symaddr(g_W_e0);
    float* W_e1 = symaddr(g_W_e1);
    float* W_e2 = symaddr(g_W_e2);
    float* W_d0 = symaddr(g_W_d0);
    float* W_d1 = symaddr(g_W_d1);
    float* W_d2 = symaddr(g_W_d2);

    const dim3 blk(256);

    cnorm_k<<<64, blk>>>(codebook);   // + stats reset

    BWAll P;
    P.L[0] = { e0_bw, e0_aw, e0_ab, W_e0, 64*128 };
    P.L[1] = { e1_bw, e1_aw, e1_ab, W_e1, 128*64 };
    P.L[2] = { e2_bw, e2_aw, e2_ab, W_e2, 256*128 };
    P.L[3] = { d0_bw, d0_aw, d0_ab, W_d0, 128*256 };
    P.L[4] = { d1_bw, d1_aw, d1_ab, W_d1, 64*128 };
    P.L[5] = { d2_bw, d2_aw, d2_ab, W_d2, 128*64 };
    P.off[0] = 0;
    for (int l = 0; l < 6; l++) P.off[l+1] = P.off[l] + P.L[l].E;
    build_w_all_k<<<(98304/256)*4, blk>>>(P, adapt);

    // encoder (R12 config)
    liquid_gemm_k<128,  64, 1><<<dim3(32, 1, BATCH), blk>>>(x,    W_e0, e0_bb, bufA);
    liquid_gemm_k< 64, 128, 1><<<dim3(32, 2, BATCH), blk>>>(bufA, W_e1, e1_bb, bufB);
    liquid_gemm_k<128, 256, 0><<<dim3(32, 4, BATCH), blk>>>(bufB, W_e2, e2_bb, bufA);

    // vector quantization: 512 threads / 128 tokens per block
    const int vq_smem = (256*132 + 2*16*68 + 128*17 + 128*17 + 128 + 128 + 16) * (int)sizeof(float); // ~162 KB
    cudaFuncSetAttribute(vq_argmin_k, cudaFuncAttributeMaxDynamicSharedMemorySize, vq_smem);
    vq_argmin_k<<<NTOK/128, 512, vq_smem>>>(bufA, codebook, zq);

    // decoder (R12 config)
    liquid_gemm_k<256, 128, 1><<<dim3(32, 2, BATCH), blk>>>(zq,   W_d0, d0_bb, bufB);
    liquid_gemm_k<128,  64, 1><<<dim3(32, 1, BATCH), blk>>>(bufB, W_d1, d1_bb, bufA);
    liquid_gemm_k< 64, 128, 2><<<dim3(32, 2, BATCH), blk>>>(bufA, W_d2, d2_bb, recon);

    finalize_k<<<1, 32>>>(scalars);
}

// round 17
// speedup vs baseline: 1.1315x; 1.0725x over previous
#include <cuda_runtime.h>
#include <math.h>

#define BATCH 32
#define SEQ   4096
#define NTOK  (BATCH*SEQ)      // 131072
#define AD    64
#define DCODE 256
#define KCODES 512

// ---------------- packed dual-fp32 FMA (bit-identical per-lane IEEE fma) ----
__device__ __forceinline__ void ffma2(float2& acc, float2 a, float2 b)
{
    unsigned long long A = *reinterpret_cast<unsigned long long*>(&a);
    unsigned long long B = *reinterpret_cast<unsigned long long*>(&b);
    unsigned long long C = *reinterpret_cast<unsigned long long*>(&acc);
    asm("fma.rn.f32x2 %0, %1, %2, %0;" : "+l"(C) : "l"(A), "l"(B));
    acc = *reinterpret_cast<float2*>(&C);
}

// ---------------- warp row-reduce for sum(x^2) (BIT-FROZEN since R7) --------
__device__ __forceinline__ float warp_sumsq_256(const float* __restrict__ row, int lane)
{
    float ax = 0.f, ay = 0.f;
#pragma unroll
    for (int i = 0; i < 4; i++) {
        float v0 = row[64*i + 2*lane + 0];
        float v1 = row[64*i + 2*lane + 1];
        ax = __fadd_rn(ax, __fmul_rn(v0, v0));
        ay = __fadd_rn(ay, __fmul_rn(v1, v1));
    }
    float s = __fadd_rn(ax, ay);
#pragma unroll
    for (int off = 16; off > 0; off >>= 1) {
        float o = __shfl_down_sync(0xffffffffu, s, off);
        s = __fadd_rn(s, o);
    }
    return s;   // valid in lane 0
}

// ---------------- scratch (__device__ globals: allocation-free) -------------
__device__ float g_bufA[NTOK*256];   // widest intermediate (z_e)
__device__ float g_bufB[NTOK*128];
__device__ float g_W_e0[BATCH*64*128];
__device__ float g_W_e1[BATCH*128*64];
__device__ float g_W_e2[BATCH*256*128];
__device__ float g_W_d0[BATCH*128*256];
__device__ float g_W_d1[BATCH*64*128];
__device__ float g_W_d2[BATCH*128*64];
__device__ float        g_cnorm[KCODES];
__device__ unsigned int g_hist[KCODES];
__device__ double       g_sumsq;

// ---------------- codebook norms (FROZEN) + stats reset ---------------------
__global__ __launch_bounds__(256) void cnorm_k(const float* __restrict__ CB)
{
    if (blockIdx.x == 0) {
        for (int i = threadIdx.x; i < KCODES; i += 256) g_hist[i] = 0u;
        if (threadIdx.x == 0) g_sumsq = 0.0;
    }
    int warp = (blockIdx.x * blockDim.x + threadIdx.x) >> 5;  // = code index
    int lane = threadIdx.x & 31;
    if (warp < KCODES) {
        float s = warp_sumsq_256(CB + (long)warp * DCODE, lane);
        if (lane == 0) g_cnorm[warp] = s;
    }
}

// ---------------- merged per-batch weight materialization (FROZEN math) -----
struct BWLayer { const float* bw; const float* aw; const float* ab; float* W; int E; };
struct BWAll   { BWLayer L[6]; int off[7]; };

__global__ __launch_bounds__(256) void build_w_all_k(BWAll P, const float* __restrict__ adapt)
{
    __shared__ float ad[BATCH*AD];
    for (int i = threadIdx.x; i < BATCH*AD; i += 256) ad[i] = adapt[i];
    __syncthreads();

    const int bgroup = blockIdx.x & 3;          // 8 batches per group
    const int ebid   = blockIdx.x >> 2;
    const int eg     = ebid * 256 + threadIdx.x;

    int layer = 0;
#pragma unroll
    for (int l = 0; l < 6; l++) if (eg >= P.off[l+1]) layer = l + 1;
    const BWLayer& L = P.L[layer];
    const int e = eg - P.off[layer];

    float awr[AD];
#pragma unroll
    for (int d = 0; d < AD; d += 4) {
        float4 v = *reinterpret_cast<const float4*>(L.aw + (long)e*AD + d);
        awr[d] = v.x; awr[d+1] = v.y; awr[d+2] = v.z; awr[d+3] = v.w;
    }
    const float base = L.bw[e];
    const float abv  = L.ab[e];
    for (int b = bgroup*8; b < bgroup*8 + 8; b++) {
        float acc = 0.f;
#pragma unroll
        for (int d = 0; d < AD; d++) acc = fmaf(ad[b*AD + d], awr[d], acc);
        acc = __fadd_rn(acc, abv);
        L.W[(long)b*L.E + e] = __fadd_rn(base, acc);
    }
}

// ---------------- liquid GEMM 128x64, double-buffered (R12 config, FROZEN) --
template<int IN, int OUT, int ACT>
__global__ __launch_bounds__(256) void liquid_gemm_k(
    const float* __restrict__ X, const float* __restrict__ Wall,
    const float* __restrict__ bb, float* __restrict__ Y)
{
    const int b  = blockIdx.z;
    const int m0 = blockIdx.x * 128;
    const int n0 = blockIdx.y * 64;
    const float* Xb = X    + ((long)b*SEQ + m0) * IN;
    const float* Wb = Wall + (long)b*OUT*IN + (long)n0*IN;
    float*       Yb = Y    + ((long)b*SEQ + m0) * OUT + n0;

    __shared__ float As[2][16][132];
    __shared__ float Bs[2][16][68];

    const int tid  = threadIdx.x;
    const int ar0 = tid >> 1;
    const int aq0 = (tid & 1) * 8;
    const int br  = tid >> 2;
    const int bq  = (tid & 3) * 4;
    const int ty  = tid >> 4;
    const int tx  = tid & 15;

    float2 acc2[8][2];
#pragma unroll
    for (int i = 0; i < 8; i++) { acc2[i][0] = make_float2(0.f,0.f); acc2[i][1] = make_float2(0.f,0.f); }

    float4 av0 = *reinterpret_cast<const float4*>(Xb + (long)ar0*IN + aq0);
    float4 av1 = *reinterpret_cast<const float4*>(Xb + (long)ar0*IN + aq0 + 4);
    float4 bv  = *reinterpret_cast<const float4*>(Wb + (long)br*IN + bq);

    int cur = 0;
    for (int k0 = 0; k0 < IN; k0 += 16) {
        As[cur][aq0+0][ar0] = av0.x; As[cur][aq0+1][ar0] = av0.y;
        As[cur][aq0+2][ar0] = av0.z; As[cur][aq0+3][ar0] = av0.w;
        As[cur][aq0+4][ar0] = av1.x; As[cur][aq0+5][ar0] = av1.y;
        As[cur][aq0+6][ar0] = av1.z; As[cur][aq0+7][ar0] = av1.w;
        Bs[cur][bq+0][br] = bv.x; Bs[cur][bq+1][br] = bv.y;
        Bs[cur][bq+2][br] = bv.z; Bs[cur][bq+3][br] = bv.w;
        __syncthreads();
        if (k0 + 16 < IN) {
            av0 = *reinterpret_cast<const float4*>(Xb + (long)ar0*IN + k0 + 16 + aq0);
            av1 = *reinterpret_cast<const float4*>(Xb + (long)ar0*IN + k0 + 16 + aq0 + 4);
            bv  = *reinterpret_cast<const float4*>(Wb + (long)br*IN + k0 + 16 + bq);
        }
#pragma unroll
        for (int k = 0; k < 16; k++) {
            float4 alo = *reinterpret_cast<const float4*>(&As[cur][k][ty*8]);
            float4 ahi = *reinterpret_cast<const float4*>(&As[cur][k][ty*8+4]);
            float4 q   = *reinterpret_cast<const float4*>(&Bs[cur][k][tx*4]);
            float2 b0 = make_float2(q.x, q.y);
            float2 b1 = make_float2(q.z, q.w);
            float am[8] = {alo.x, alo.y, alo.z, alo.w, ahi.x, ahi.y, ahi.z, ahi.w};
#pragma unroll
            for (int i = 0; i < 8; i++) {
                float2 ai = make_float2(am[i], am[i]);
                ffma2(acc2[i][0], ai, b0);
                ffma2(acc2[i][1], ai, b1);
            }
        }
        cur ^= 1;
    }

    float bias[4];
#pragma unroll
    for (int j = 0; j < 4; j++) bias[j] = bb[n0 + tx*4 + j];

#pragma unroll
    for (int i = 0; i < 8; i++) {
        const int m = ty*8 + i;
        float accv[4] = { acc2[i][0].x, acc2[i][0].y, acc2[i][1].x, acc2[i][1].y };
#pragma unroll
        for (int j = 0; j < 4; j++) {
            float v = __fadd_rn(accv[j], bias[j]);
            if (ACT == 1) v = fmaxf(v, 0.f);
            if (ACT == 2) v = 1.f / (1.f + expf(-v));
            Yb[(long)m*OUT + tx*4 + j] = v;
        }
    }
}

// ---------------- VQ argmin + fused gather/loss/hist -------------------------
// R12 arithmetic BIT-FROZEN (4-phase interleaved ffma2 chains by k mod 4,
// fold ((c0+c1)+c2)+c3, score fl(fl(zn+cn)-fl(2*dot)), ascending first-min,
// zn warp pattern, per-element gather formulas).
// R17 scheduling: 32-k B chunks (half the barriers); gather vectorized to
// LDG.128/STG.128 (4 d per thread x 16 tokens).
__global__ __launch_bounds__(256) void vq_argmin_k(
    const float* __restrict__ Z, const float* __restrict__ CB,
    float* __restrict__ zq_out)
{
    extern __shared__ float sm[];
    float (*Zt)[68]    = (float (*)[68])    sm;                         // 256 x 68
    float (*Bs)[32][68]= (float (*)[32][68])(sm + 256*68);              // 2 x 32 x 68
    float (*rv)[17]    = (float (*)[17])    (sm + 256*68 + 2*32*68);    // 64 x 17
    int   (*ri)[17]    = (int   (*)[17])    (sm + 256*68 + 2*32*68 + 64*17);
    float *zn_s        = (float*)           (sm + 256*68 + 2*32*68 + 64*17 + 64*17);
    int   *idx_s       = (int*)             (sm + 256*68 + 2*32*68 + 64*17 + 64*17 + 64);
    float *ws          = (float*)           (sm + 256*68 + 2*32*68 + 64*17 + 64*17 + 64 + 64);

    const int m0  = blockIdx.x * 64;
    const int tid = threadIdx.x;

    // Per-token ||z||^2 from GLOBAL memory — FROZEN values & op order.
    // (Also warms L1 for the staging pass right below.)
    {
        const int warp = tid >> 5;
        const int lane = tid & 31;
        for (int j = 0; j < 8; j++) {
            int tok = warp * 8 + j;
            float s = warp_sumsq_256(Z + (long)(m0 + tok)*DCODE, lane);
            if (lane == 0) zn_s[tok] = s;
        }
    }

    // Stage Z transposed: Zt[k][m].
    for (int i = tid; i < 64*64; i += 256) {
        int m = i >> 6;
        int q = (i & 63) * 4;
        float4 v = *reinterpret_cast<const float4*>(Z + (long)(m0 + m)*DCODE + q);
        Zt[q+0][m] = v.x; Zt[q+1][m] = v.y; Zt[q+2][m] = v.z; Zt[q+3][m] = v.w;
    }
    __syncthreads();

    const int lrow = tid >> 2;          // code row 0..63
    const int lk4  = (tid & 3) * 4;     // k offsets 0..12 (and +16)
    const int ty   = tid >> 4;
    const int tx   = tid & 15;

    float zn[4];
#pragma unroll
    for (int i = 0; i < 4; i++) zn[i] = zn_s[ty*4 + i];

    float bestv[4];
    int   besti[4];
#pragma unroll
    for (int i = 0; i < 4; i++) { bestv[i] = 3.4e38f; besti[i] = 0; }

    int cur = 0;
    float4 pb0 = *reinterpret_cast<const float4*>(CB + (long)lrow*DCODE + lk4);       // n0=0,k0=0
    float4 pb1 = *reinterpret_cast<const float4*>(CB + (long)lrow*DCODE + 16 + lk4);

    for (int n0 = 0; n0 < KCODES; n0 += 64) {
        float2 acc[4][4][2];   // [phase][token][half] — FROZEN 4-phase chains
#pragma unroll
        for (int p = 0; p < 4; p++)
#pragma unroll
            for (int i = 0; i < 4; i++) {
                acc[p][i][0] = make_float2(0.f,0.f);
                acc[p][i][1] = make_float2(0.f,0.f);
            }

        for (int k0 = 0; k0 < DCODE; k0 += 32) {
            Bs[cur][lk4+0][lrow] = pb0.x; Bs[cur][lk4+1][lrow] = pb0.y;
            Bs[cur][lk4+2][lrow] = pb0.z; Bs[cur][lk4+3][lrow] = pb0.w;
            Bs[cur][16+lk4+0][lrow] = pb1.x; Bs[cur][16+lk4+1][lrow] = pb1.y;
            Bs[cur][16+lk4+2][lrow] = pb1.z; Bs[cur][16+lk4+3][lrow] = pb1.w;
            __syncthreads();
            {
                int nk = k0 + 32, nn = n0;
                if (nk == DCODE) { nk = 0; nn = n0 + 64; }
                if (nn < KCODES) {
                    const float* src = CB + (long)(nn + lrow)*DCODE + nk + lk4;
                    pb0 = *reinterpret_cast<const float4*>(src);
                    pb1 = *reinterpret_cast<const float4*>(src + 16);
                }
            }
#pragma unroll
            for (int k = 0; k < 32; k++) {
                const int p = k & 3;                    // == (k0+k)&3 since 32|k0
                float4 a = *reinterpret_cast<const float4*>(&Zt[k0+k][ty*4]);
                float4 q = *reinterpret_cast<const float4*>(&Bs[cur][k][tx*4]);
                float2 b0 = make_float2(q.x, q.y);
                float2 b1 = make_float2(q.z, q.w);
                float2 a0 = make_float2(a.x, a.x);
                float2 a1 = make_float2(a.y, a.y);
                float2 a2 = make_float2(a.z, a.z);
                float2 a3 = make_float2(a.w, a.w);
                ffma2(acc[p][0][0], a0, b0); ffma2(acc[p][0][1], a0, b1);
                ffma2(acc[p][1][0], a1, b0); ffma2(acc[p][1][1], a1, b1);
                ffma2(acc[p][2][0], a2, b0); ffma2(acc[p][2][1], a2, b1);
                ffma2(acc[p][3][0], a3, b0); ffma2(acc[p][3][1], a3, b1);
            }
            cur ^= 1;
        }
#pragma unroll
        for (int j = 0; j < 4; j++) {
            const int code = n0 + tx*4 + j;
            const float cn = g_cnorm[code];
#pragma unroll
            for (int i = 0; i < 4; i++) {
                const int h = j >> 1;
                float c0 = (j & 1) ? acc[0][i][h].y : acc[0][i][h].x;
                float c1 = (j & 1) ? acc[1][i][h].y : acc[1][i][h].x;
                float c2 = (j & 1) ? acc[2][i][h].y : acc[2][i][h].x;
                float c3 = (j & 1) ? acc[3][i][h].y : acc[3][i][h].x;
                float dot = __fadd_rn(__fadd_rn(__fadd_rn(c0, c1), c2), c3);
                float t = __fadd_rn(zn[i], cn);                    // fl(zn + cn)
                float s = __fadd_rn(t, -__fmul_rn(2.f, dot));      // fl(t - 2*dot)
                if (s < bestv[i]) { bestv[i] = s; besti[i] = code; }
            }
        }
    }

    __syncthreads();
#pragma unroll
    for (int i = 0; i < 4; i++) {
        rv[ty*4 + i][tx] = bestv[i];
        ri[ty*4 + i][tx] = besti[i];
    }
    __syncthreads();

    if (tid < 64) {
        float bv2 = rv[tid][0]; int bi = ri[tid][0];
#pragma unroll
        for (int x = 1; x < 16; x++) {
            float v = rv[tid][x]; int ii = ri[tid][x];
            if (v < bv2 || (v == bv2 && ii < bi)) { bv2 = v; bi = ii; }
        }
        idx_s[tid] = bi;
    }
    __syncthreads();

    // -------- fused gather (vectorized): z_q, loss, histogram --------------
    // Thread handles d = (tid&63)*4..+3 for 16 tokens (tid>>6)*16..+15.
    // Per-element formulas FROZEN; lsum grouping affects scalars only.
    {
        const int d4    = (tid & 63) * 4;
        const int tbase = (tid >> 6) * 16;
        float lsum = 0.f;
        for (int t = 0; t < 16; t++) {
            const int token = tbase + t;
            const int idx   = idx_s[token];
            float4 qv = *reinterpret_cast<const float4*>(CB + (long)idx*DCODE + d4);
            float z0 = Zt[d4+0][token], z1 = Zt[d4+1][token];
            float z2 = Zt[d4+2][token], z3 = Zt[d4+3][token];
            float f0 = __fadd_rn(qv.x, -z0);
            float f1 = __fadd_rn(qv.y, -z1);
            float f2 = __fadd_rn(qv.z, -z2);
            float f3 = __fadd_rn(qv.w, -z3);
            lsum += f0*f0; lsum += f1*f1; lsum += f2*f2; lsum += f3*f3;
            float4 o;
            o.x = __fadd_rn(z0, f0); o.y = __fadd_rn(z1, f1);
            o.z = __fadd_rn(z2, f2); o.w = __fadd_rn(z3, f3);
            *reinterpret_cast<float4*>(zq_out + (long)(m0 + token)*DCODE + d4) = o;
        }
#pragma unroll
        for (int o = 16; o > 0; o >>= 1) lsum += __shfl_xor_sync(0xffffffffu, lsum, o);
        if ((tid & 31) == 0) ws[tid >> 5] = lsum;
    }
    __syncthreads();
    if (tid == 0) {
        float s = 0.f;
#pragma unroll
        for (int w = 0; w < 8; w++) s += ws[w];
        atomicAdd(&g_sumsq, (double)s);
    }
    if (tid < 64) atomicAdd(&g_hist[idx_s[tid]], 1u);
}

// ---------------- scalars: vq_loss, perplexity ------------------------------
__global__ void finalize_k(float* __restrict__ scalars)
{
    if (threadIdx.x == 0 && blockIdx.x == 0) {
        double mse = g_sumsq / (double)((long)NTOK * DCODE);
        scalars[0] = (float)(mse * 1.25);
        double H = 0.0;
        for (int k = 0; k < KCODES; k++) {
            double p = (double)g_hist[k] / (double)NTOK;
            H -= p * log(p + 1e-10);
        }
        scalars[1] = (float)exp(H);
    }
}

// ---------------- launch --------------------------------------------------
static float* symaddr(const void* sym)
{
    void* p = nullptr;
    cudaGetSymbolAddress(&p, sym);
    return (float*)p;
}

extern "C" void kernel_launch(void* const* d_in, const int* in_sizes, int n_in,
                              void* d_out, int out_size)
{
    (void)in_sizes; (void)n_in; (void)out_size;

    const float* x        = (const float*)d_in[0];
    const float* adapt    = (const float*)d_in[1];
    const float* e0_bw = (const float*)d_in[2],  *e0_bb = (const float*)d_in[3],
               * e0_aw = (const float*)d_in[4],  *e0_ab = (const float*)d_in[5];
    const float* e1_bw = (const float*)d_in[6],  *e1_bb = (const float*)d_in[7],
               * e1_aw = (const float*)d_in[8],  *e1_ab = (const float*)d_in[9];
    const float* e2_bw = (const float*)d_in[10], *e2_bb = (const float*)d_in[11],
               * e2_aw = (const float*)d_in[12], *e2_ab = (const float*)d_in[13];
    const float* d0_bw = (const float*)d_in[14], *d0_bb = (const float*)d_in[15],
               * d0_aw = (const float*)d_in[16], *d0_ab = (const float*)d_in[17];
    const float* d1_bw = (const float*)d_in[18], *d1_bb = (const float*)d_in[19],
               * d1_aw = (const float*)d_in[20], *d1_ab = (const float*)d_in[21];
    const float* d2_bw = (const float*)d_in[22], *d2_bb = (const float*)d_in[23],
               * d2_aw = (const float*)d_in[24], *d2_ab = (const float*)d_in[25];
    const float* codebook = (const float*)d_in[26];

    float* out     = (float*)d_out;
    float* zq      = out;                       // [32,4096,256]
    float* scalars = out + (long)NTOK * DCODE;  // loss, perplexity
    float* recon   = scalars + 2;               // [32,4096,128]

    float* bufA = symaddr(g_bufA);
    float* bufB = symaddr(g_bufB);
    float* W_e0 = symaddr(g_W_e0);
    float* W_e1 = symaddr(g_W_e1);
    float* W_e2 = symaddr(g_W_e2);
    float* W_d0 = symaddr(g_W_d0);
    float* W_d1 = symaddr(g_W_d1);
    float* W_d2 = symaddr(g_W_d2);

    const dim3 blk(256);

    cnorm_k<<<64, blk>>>(codebook);   // + stats reset

    BWAll P;
    P.L[0] = { e0_bw, e0_aw, e0_ab, W_e0, 64*128 };
    P.L[1] = { e1_bw, e1_aw, e1_ab, W_e1, 128*64 };
    P.L[2] = { e2_bw, e2_aw, e2_ab, W_e2, 256*128 };
    P.L[3] = { d0_bw, d0_aw, d0_ab, W_d0, 128*256 };
    P.L[4] = { d1_bw, d1_aw, d1_ab, W_d1, 64*128 };
    P.L[5] = { d2_bw, d2_aw, d2_ab, W_d2, 128*64 };
    P.off[0] = 0;
    for (int l = 0; l < 6; l++) P.off[l+1] = P.off[l] + P.L[l].E;
    build_w_all_k<<<(98304/256)*4, blk>>>(P, adapt);

    // encoder (R12 config)
    liquid_gemm_k<128,  64, 1><<<dim3(32, 1, BATCH), blk>>>(x,    W_e0, e0_bb, bufA);
    liquid_gemm_k< 64, 128, 1><<<dim3(32, 2, BATCH), blk>>>(bufA, W_e1, e1_bb, bufB);
    liquid_gemm_k<128, 256, 0><<<dim3(32, 4, BATCH), blk>>>(bufB, W_e2, e2_bb, bufA);

    // vector quantization (argmin + fused gather/loss/hist)
    const int vq_smem = (256*68 + 2*32*68 + 64*17 + 64*17 + 64 + 64 + 8) * (int)sizeof(float); // 96.3 KB
    cudaFuncSetAttribute(vq_argmin_k, cudaFuncAttributeMaxDynamicSharedMemorySize, vq_smem);
    vq_argmin_k<<<NTOK/64, blk, vq_smem>>>(bufA, codebook, zq);

    // decoder (R12 config)
    liquid_gemm_k<256, 128, 1><<<dim3(32, 2, BATCH), blk>>>(zq,   W_d0, d0_bb, bufB);
    liquid_gemm_k<128,  64, 1><<<dim3(32, 1, BATCH), blk>>>(bufB, W_d1, d1_bb, bufA);
    liquid_gemm_k< 64, 128, 2><<<dim3(32, 2, BATCH), blk>>>(bufA, W_d2, d2_bb, recon);

    finalize_k<<<1, 32>>>(scalars);
}